// round 2
// baseline (speedup 1.0000x reference)
#include <cuda_runtime.h>
#include <cstdint>

// ROI Align, P=7, S=2, SCALE=0.125
// x: (8, 256, 100, 100) fp32   rois: (512, 5) fp32   out: (512, 256, 7, 7) fp32
//
// Block = (roi, group of 16 channels). Stage each channel's ROI patch
// (<=26x26 floats, avg ~14x14) into smem with coalesced loads, precompute
// the 14+14 per-axis bilinear terms once per block, then compute 16*49
// outputs with smem gathers only.

#define C_    256
#define H_    100
#define W_    100
#define P_    7
#define HW_   (H_ * W_)
#define CB    16          // channels per block
#define PSTR  27          // patch row stride (odd -> bank-friendly)
#define PROWS 26
#define PWORDS (PROWS * PSTR)
#define NTHREADS 256

__device__ __forceinline__ void axis_terms(float c, int L,
                                           int& lo, int& hi,
                                           float& wlo, float& whi) {
    bool valid = (c > -1.0f) && (c < (float)L);
    float cc = fminf(fmaxf(c, 0.0f), (float)(L - 1));
    int l = (int)floorf(cc);
    if (l > L - 1) l = L - 1;
    int h = min(l + 1, L - 1);
    float frac = cc - (float)l;
    lo = l; hi = h;
    wlo = valid ? (1.0f - frac) : 0.0f;
    whi = valid ? frac : 0.0f;
}

__device__ __forceinline__ float bilin(const float* __restrict__ p,
                                       int2 yy, float2 wy,
                                       int2 xx, float2 wx) {
    float lo = fmaf(wx.x, p[yy.x + xx.x], 0.0f) + wx.y * p[yy.x + xx.y];
    float hi = wx.x * p[yy.y + xx.x] + wx.y * p[yy.y + xx.y];
    return wy.x * lo + wy.y * hi;
}

__global__ void __launch_bounds__(NTHREADS)
roi_align_smem(const float* __restrict__ x,
               const float* __restrict__ rois,
               float* __restrict__ out) {
    __shared__ float patch[CB][PWORDS];    // 16 * 26*27 * 4B = 44928 B
    __shared__ int2   yo[14];              // (lo*PSTR, hi*PSTR), patch-relative
    __shared__ float2 yw[14];
    __shared__ int2   xo[14];              // (lo, hi), patch-relative
    __shared__ float2 xw[14];

    const int r   = blockIdx.x >> 4;       // roi
    const int cg  = blockIdx.x & 15;       // channel group
    const int tid = threadIdx.x;

    // --- ROI params (broadcast) ---
    const float* roi = rois + (size_t)r * 5;
    float r0 = __ldg(roi + 0);
    float r1 = __ldg(roi + 1);
    float r2 = __ldg(roi + 2);
    float r3 = __ldg(roi + 3);
    float r4 = __ldg(roi + 4);

    const int b = (int)r0;
    const float sx = r1 * 0.125f - 0.5f;
    const float sy = r2 * 0.125f - 0.5f;
    const float bw = (r3 * 0.125f - 0.5f - sx) * (1.0f / 7.0f);
    const float bh = (r4 * 0.125f - 0.5f - sy) * (1.0f / 7.0f);

    // Patch bounds from extremal samples (positions monotone, bw/bh > 0).
    // Every thread computes these redundantly (registers only).
    int y0, x0, ny, nx;
    {
        int lo0, hi0, lo1, hi1; float d0, d1, d2, d3;
        axis_terms(fmaf(0.25f, bh, sy), H_, lo0, hi0, d0, d1);
        axis_terms(fmaf(6.75f, bh, sy), H_, lo1, hi1, d2, d3);
        y0 = lo0; ny = hi1 - lo0 + 1;
        axis_terms(fmaf(0.25f, bw, sx), W_, lo0, hi0, d0, d1);
        axis_terms(fmaf(6.75f, bw, sx), W_, lo1, hi1, d2, d3);
        x0 = lo0; nx = hi1 - lo0 + 1;
    }

    // --- Per-axis bilinear terms, once per block ---
    if (tid < 14) {
        int s = tid;
        float pos = fmaf((float)(s >> 1) + ((s & 1) ? 0.75f : 0.25f), bh, sy);
        int lo, hi; float wlo, whi;
        axis_terms(pos, H_, lo, hi, wlo, whi);
        yo[s] = make_int2((lo - y0) * PSTR, (hi - y0) * PSTR);
        yw[s] = make_float2(wlo, whi);
    } else if (tid >= 16 && tid < 30) {
        int s = tid - 16;
        float pos = fmaf((float)(s >> 1) + ((s & 1) ? 0.75f : 0.25f), bw, sx);
        int lo, hi; float wlo, whi;
        axis_terms(pos, W_, lo, hi, wlo, whi);
        xo[s] = make_int2(lo - x0, hi - x0);
        xw[s] = make_float2(wlo, whi);
    }

    // --- Stage patches: one warp handles 2 channels ---
    {
        const int warp = tid >> 5;
        const int lane = tid & 31;
        const int npix = ny * nx;
        for (int cc = warp; cc < CB; cc += (NTHREADS / 32)) {
            const float* src = x + ((size_t)(b * C_ + cg * CB + cc)) * HW_
                                 + y0 * W_ + x0;
            float* dst = patch[cc];
            for (int i = lane; i < npix; i += 32) {
                int yy = i / nx;
                int xx = i - yy * nx;
                dst[yy * PSTR + xx] = __ldg(src + yy * W_ + xx);
            }
        }
    }
    __syncthreads();

    // --- Compute 16*49 outputs ---
    float* outr = out + (size_t)r * (C_ * P_ * P_) + (size_t)cg * (CB * P_ * P_);
#pragma unroll
    for (int o = tid; o < CB * P_ * P_; o += NTHREADS) {
        int c   = o / 49;
        int bin = o - c * 49;
        int ph  = bin / 7;
        int pw  = bin - ph * 7;

        const float* p = patch[c];
        int2   ya = yo[2 * ph], yb = yo[2 * ph + 1];
        float2 wa = yw[2 * ph], wb = yw[2 * ph + 1];
        int2   xa = xo[2 * pw], xb = xo[2 * pw + 1];
        float2 va = xw[2 * pw], vb = xw[2 * pw + 1];

        float acc = bilin(p, ya, wa, xa, va)
                  + bilin(p, ya, wa, xb, vb)
                  + bilin(p, yb, wb, xa, va)
                  + bilin(p, yb, wb, xb, vb);

        outr[o] = acc * 0.25f;
    }
}

extern "C" void kernel_launch(void* const* d_in, const int* in_sizes, int n_in,
                              void* d_out, int out_size) {
    const float* x    = (const float*)d_in[0];
    const float* rois = (const float*)d_in[1];
    float* out = (float*)d_out;

    // 512 rois * 16 channel-groups
    roi_align_smem<<<512 * (C_ / CB), NTHREADS>>>(x, rois, out);
}

// round 3
// speedup vs baseline: 1.3323x; 1.3323x over previous
#include <cuda_runtime.h>
#include <cstdint>

// ROI Align, P=7, S=2, SCALE=0.125
// x: (8, 256, 100, 100) fp32   rois: (512, 5) fp32   out: (512, 256, 7, 7) fp32
//
// Two kernels:
//  1) geom_kernel: per (roi, axis-sample) bilinear terms -> __device__ table.
//  2) roi_main: direct gather; block == 256 outputs inside one roi, geometry
//     broadcast via 448B of smem. 16 L1-hit gathers + ~20 FMA per output.

#define C_   256
#define H_   100
#define W_   100
#define HW_  10000
#define R_   512
#define TOTAL (R_ * C_ * 49)

__device__ int4 g_geom[R_][28];   // [0..13]=y terms {loW, hiW, wlo, whi}
                                  // [14..27]=x terms {xbase, w0, w1, roiBase}

__device__ __forceinline__ void axis_terms(float c, int L,
                                           int& lo, int& hi,
                                           float& wlo, float& whi) {
    bool valid = (c > -1.0f) && (c < (float)L);
    float cc = fminf(fmaxf(c, 0.0f), (float)(L - 1));
    int l = (int)floorf(cc);
    if (l > L - 1) l = L - 1;
    int h = min(l + 1, L - 1);
    float frac = cc - (float)l;
    lo = l; hi = h;
    wlo = valid ? (1.0f - frac) : 0.0f;
    whi = valid ? frac : 0.0f;
}

__global__ void geom_kernel(const float* __restrict__ rois) {
    int t = blockIdx.x * blockDim.x + threadIdx.x;
    if (t >= R_ * 28) return;
    int r = t / 28;
    int s = t - r * 28;

    const float* roi = rois + (size_t)r * 5;
    float r0 = __ldg(roi + 0);
    float r1 = __ldg(roi + 1);
    float r2 = __ldg(roi + 2);
    float r3 = __ldg(roi + 3);
    float r4 = __ldg(roi + 4);

    int b = (int)r0;
    float sx = r1 * 0.125f - 0.5f;
    float sy = r2 * 0.125f - 0.5f;
    float bw = (r3 * 0.125f - 0.5f - sx) * (1.0f / 7.0f);
    float bh = (r4 * 0.125f - 0.5f - sy) * (1.0f / 7.0f);

    int4 e;
    if (s < 14) {
        float pos = fmaf((float)(s >> 1) + ((s & 1) ? 0.75f : 0.25f), bh, sy);
        int lo, hi; float w0, w1;
        axis_terms(pos, H_, lo, hi, w0, w1);
        e = make_int4(lo * W_, hi * W_, __float_as_int(w0), __float_as_int(w1));
    } else {
        int s2 = s - 14;
        float pos = fmaf((float)(s2 >> 1) + ((s2 & 1) ? 0.75f : 0.25f), bw, sx);
        int lo, hi; float w0, w1;
        axis_terms(pos, W_, lo, hi, w0, w1);
        // Fold hi==lo (right edge, lo==W-1) into weights on base xb so the
        // consumer always reads {xb, xb+1}.
        int xb; float v0, v1;
        if (lo == W_ - 1) { xb = W_ - 2; v0 = 0.0f; v1 = w0 + w1; }
        else              { xb = lo;     v0 = w0;   v1 = w1; }
        e = make_int4(xb, __float_as_int(v0), __float_as_int(v1), b * C_ * HW_);
    }
    g_geom[r][s] = e;
}

__global__ void __launch_bounds__(256)
roi_main(const float* __restrict__ x, float* __restrict__ out) {
    __shared__ int4 sg[28];

    // 49 blocks per roi (12544 outputs / 256) -> r uniform across block.
    int r = blockIdx.x / 49;
    if (threadIdx.x < 28) sg[threadIdx.x] = g_geom[r][threadIdx.x];
    __syncthreads();

    int o = blockIdx.x * 256 + threadIdx.x;
    int bin = o % 49;
    int c   = (o / 49) & (C_ - 1);   // o/49 == r*256 + c
    int ph  = bin / 7;
    int pw  = bin - ph * 7;

    int4 gy0 = sg[2 * ph];
    int4 gy1 = sg[2 * ph + 1];
    int4 gx0 = sg[14 + 2 * pw];
    int4 gx1 = sg[14 + 2 * pw + 1];

    const float* p = x + gx0.w + c * HW_;
    const float* rA0 = p + gy0.x;
    const float* rA1 = p + gy0.y;
    const float* rB0 = p + gy1.x;
    const float* rB1 = p + gy1.y;

    const int   xa   = gx0.x,                 xb   = gx1.x;
    const float wx00 = __int_as_float(gx0.y), wx01 = __int_as_float(gx0.z);
    const float wx10 = __int_as_float(gx1.y), wx11 = __int_as_float(gx1.z);

    float hA0 = wx00 * __ldg(rA0 + xa) + wx01 * __ldg(rA0 + xa + 1)
              + wx10 * __ldg(rA0 + xb) + wx11 * __ldg(rA0 + xb + 1);
    float hA1 = wx00 * __ldg(rA1 + xa) + wx01 * __ldg(rA1 + xa + 1)
              + wx10 * __ldg(rA1 + xb) + wx11 * __ldg(rA1 + xb + 1);
    float hB0 = wx00 * __ldg(rB0 + xa) + wx01 * __ldg(rB0 + xa + 1)
              + wx10 * __ldg(rB0 + xb) + wx11 * __ldg(rB0 + xb + 1);
    float hB1 = wx00 * __ldg(rB1 + xa) + wx01 * __ldg(rB1 + xa + 1)
              + wx10 * __ldg(rB1 + xb) + wx11 * __ldg(rB1 + xb + 1);

    float acc = __int_as_float(gy0.z) * hA0 + __int_as_float(gy0.w) * hA1
              + __int_as_float(gy1.z) * hB0 + __int_as_float(gy1.w) * hB1;

    out[o] = acc * 0.25f;
}

extern "C" void kernel_launch(void* const* d_in, const int* in_sizes, int n_in,
                              void* d_out, int out_size) {
    const float* x    = (const float*)d_in[0];
    const float* rois = (const float*)d_in[1];
    float* out = (float*)d_out;

    geom_kernel<<<(R_ * 28 + 255) / 256, 256>>>(rois);
    roi_main<<<TOTAL / 256, 256>>>(x, out);
}